// round 7
// baseline (speedup 1.0000x reference)
#include <cuda_runtime.h>
#include <cuda_bf16.h>

// Problem constants (match reference)
#define H_DIM   128
#define RBF_N   32
#define H2_DIM  64      // H - H//2
#define MAX_D   20.0f
#define NCOMBO  16      // 4 types x 4 distances (randint(0,4) both columns)
#define CHUNK   32      // rows per warp-chunk

// 256-bit streaming store (sm_100+): one instruction, 32B per lane,
// 1024B per warp => two full output rows per warp-instruction.
__device__ __forceinline__ void stg256_cs(float* p, float4 a, float4 b) {
    asm volatile("st.global.cs.v8.f32 [%0], {%1,%2,%3,%4,%5,%6,%7,%8};"
                 :: "l"(p),
                    "f"(a.x), "f"(a.y), "f"(a.z), "f"(a.w),
                    "f"(b.x), "f"(b.y), "f"(b.z), "f"(b.w)
                 : "memory");
}

// ---------------------------------------------------------------------------
// Single fused kernel.
// Prologue: build the 16x128 LUT in shared from the tiny weight tensors.
// Body:     interleaved 32-row chunks + attr prefetch (proven scheduling),
//           stores via st.global.cs.v8.f32: lanes 0-15 cover row 2p,
//           lanes 16-31 cover row 2p+1 -> 1024B contiguous per instruction,
//           half the store-instruction count, 2x bytes-in-flight per issue.
// ---------------------------------------------------------------------------
__global__ void __launch_bounds__(256, 8)
clique_encoder_kernel(const int2* __restrict__ attr,        // [N] (t, d)
                      const float* __restrict__ emb_table,  // [4][64]
                      const float* __restrict__ W,           // [4][32][64]
                      const float* __restrict__ b,           // [4][64]
                      float* __restrict__ out,               // [N][128]
                      int n)
{
    __shared__ float basis_s[4 * RBF_N];                 // 4 distances x 32 rbf
    __shared__ __align__(32) float lut_s[NCOMBO * H_DIM]; // 8 KB

    const int tid = threadIdx.x;

    // --- gaussian basis for the 4 possible integer distances ---
    if (tid < 4 * RBF_N) {
        const int dI = tid >> 5;
        const int k  = tid & 31;
        const float center = MAX_D * (float)k / 31.0f;
        const float diff   = (float)dI - center;
        const float inv2s2 = 0.5f * (31.0f / MAX_D) * (31.0f / MAX_D); // 1/(2*std^2)
        basis_s[tid] = __expf(-diff * diff * inv2s2);
    }
    __syncthreads();

    // --- build 16x128 LUT: 2048 entries, 8 per thread ---
    for (int e = tid; e < NCOMBO * H_DIM; e += 256) {
        const int combo = e >> 7;               // 0..15
        const int j     = e & 127;              // 0..127
        const int t  = combo >> 2;
        const int dI = combo & 3;
        float v;
        if (j < 64) {
            v = emb_table[t * 64 + j];
        } else {
            const int c = j - 64;
            float acc = b[t * H2_DIM + c];
            #pragma unroll
            for (int k = 0; k < RBF_N; k++)
                acc += basis_s[dI * RBF_N + k] * W[(t * RBF_N + k) * H2_DIM + c];
            v = acc;
        }
        lut_s[e] = v;
    }
    __syncthreads();

    // --- interleaved chunk-32 scatter, v8 stores, attr prefetch ---
    const int lane   = tid & 31;
    const int gwarp  = (blockIdx.x * blockDim.x + tid) >> 5;
    const int nwarps = (gridDim.x * blockDim.x) >> 5;

    const int nchunks = (n + CHUNK - 1) / CHUNK;   // 31250 for n=1e6 (exact)

    const int sub  = lane >> 4;                    // 0: row 2p, 1: row 2p+1
    const int l16  = lane & 15;                    // 32B segment within row

    int c = gwarp;
    int combo_next = 0;
    {   // prologue prefetch (coalesced: lane r -> row c*32+r)
        const int row = c * CHUNK + lane;
        if (c < nchunks && row < n) {
            int2 a = attr[row];
            combo_next = ((a.x & 3) << 2) | (a.y & 3);
        }
    }

    while (c < nchunks) {
        const int cn = c + nwarps;
        const int combo_cur = combo_next;          // consume previous load

        // issue NEXT chunk's attr load before this chunk's stores
        if (cn < nchunks) {
            const int row = cn * CHUNK + lane;
            combo_next = 0;
            if (row < n) {
                int2 a = attr[row];
                combo_next = ((a.x & 3) << 2) | (a.y & 3);
            }
        }

        const int base = c * CHUNK;
        if (base + CHUNK <= n) {
            // 16 iterations x (2 rows, 1024B) per warp-instruction
            #pragma unroll
            for (int p = 0; p < CHUNK / 2; p++) {
                const int myr  = 2 * p + sub;
                const int combo = __shfl_sync(0xFFFFFFFFu, combo_cur, myr);
                const float* src = &lut_s[combo * H_DIM + l16 * 8];
                float4 v0 = *(const float4*)src;
                float4 v1 = *(const float4*)(src + 4);
                stg256_cs(&out[(size_t)(base + myr) * H_DIM + l16 * 8], v0, v1);
            }
        } else {
            const int cnt = n - base;
            for (int r = 0; r < cnt; r++) {
                int combo = __shfl_sync(0xFFFFFFFFu, combo_cur, r);
                float4 v = *(const float4*)&lut_s[combo * H_DIM + lane * 4];
                __stcs((float4*)&out[(size_t)(base + r) * H_DIM + lane * 4], v);
            }
        }

        c = cn;
    }
}

// ---------------------------------------------------------------------------
// Launch
// Inputs (metadata order): clique_attr int32 [N,2], emb_table f32 [4,64],
//                          W f32 [4,32,64], b f32 [4,64]
// Output: float32 [N,128]
// ---------------------------------------------------------------------------
extern "C" void kernel_launch(void* const* d_in, const int* in_sizes, int n_in,
                              void* d_out, int out_size)
{
    const int2*  attr      = (const int2*)d_in[0];
    const float* emb_table = (const float*)d_in[1];
    const float* W         = (const float*)d_in[2];
    const float* b         = (const float*)d_in[3];
    float*       out       = (float*)d_out;

    const int n = in_sizes[0] / 2;

    const int blocks = 148 * 8;                 // one full resident wave
    clique_encoder_kernel<<<blocks, 256>>>(attr, emb_table, W, b, out, n);
}

// round 8
// speedup vs baseline: 1.2794x; 1.2794x over previous
#include <cuda_runtime.h>
#include <cuda_bf16.h>

// Problem constants (match reference)
#define H_DIM   128
#define RBF_N   32
#define H2_DIM  64      // H - H//2
#define MAX_D   20.0f
#define NCOMBO  16      // 4 types x 4 distances (randint(0,4) both columns)
#define QUANT   8       // rows per work quantum (flat axis w/ prefetch; midpoint)

// ---------------------------------------------------------------------------
// Single fused kernel (best-measured configuration, R5 structure).
// Prologue: build the 16x128 LUT in shared from the tiny weight tensors.
// Body:     interleaved grid-stride over 8-row quanta with a 1-deep
//           software-pipelined attr prefetch; each row is one STG.128
//           streaming store per lane (512B contiguous per warp-instruction).
// NOTE: st.global.v8 (R7) regressed — split-combo LDS pattern + shfl chain;
//       do not reintroduce.
// ---------------------------------------------------------------------------
__global__ void __launch_bounds__(256, 8)
clique_encoder_kernel(const int2* __restrict__ attr,        // [N] (t, d)
                      const float* __restrict__ emb_table,  // [4][64]
                      const float* __restrict__ W,           // [4][32][64]
                      const float* __restrict__ b,           // [4][64]
                      float* __restrict__ out,               // [N][128]
                      int n)
{
    __shared__ float basis_s[4 * RBF_N];        // 4 distances x 32 rbf
    __shared__ float lut_s[NCOMBO * H_DIM];     // 8 KB

    const int tid = threadIdx.x;

    // --- gaussian basis for the 4 possible integer distances ---
    if (tid < 4 * RBF_N) {
        const int dI = tid >> 5;
        const int k  = tid & 31;
        const float center = MAX_D * (float)k / 31.0f;
        const float diff   = (float)dI - center;
        const float inv2s2 = 0.5f * (31.0f / MAX_D) * (31.0f / MAX_D); // 1/(2*std^2)
        basis_s[tid] = __expf(-diff * diff * inv2s2);
    }
    __syncthreads();

    // --- build 16x128 LUT: 2048 entries, 8 per thread ---
    for (int e = tid; e < NCOMBO * H_DIM; e += 256) {
        const int combo = e >> 7;               // 0..15
        const int j     = e & 127;              // 0..127
        const int t  = combo >> 2;
        const int dI = combo & 3;
        float v;
        if (j < 64) {
            v = emb_table[t * 64 + j];
        } else {
            const int c = j - 64;
            float acc = b[t * H2_DIM + c];
            #pragma unroll
            for (int k = 0; k < RBF_N; k++)
                acc += basis_s[dI * RBF_N + k] * W[(t * RBF_N + k) * H2_DIM + c];
            v = acc;
        }
        lut_s[e] = v;
    }
    __syncthreads();

    // --- pipelined interleaved scatter ---
    const int lane   = tid & 31;
    const int gwarp  = (blockIdx.x * blockDim.x + tid) >> 5;
    const int nwarps = (gridDim.x * blockDim.x) >> 5;

    const int nqf = n / QUANT;                  // full quanta (125000 for 1e6)

    int q = gwarp;
    int combo_next = 0;
    if (q < nqf && lane < QUANT) {              // prologue prefetch (coalesced)
        int2 a = attr[q * QUANT + lane];
        combo_next = ((a.x & 3) << 2) | (a.y & 3);
    }

    while (q < nqf) {
        const int qn = q + nwarps;
        const int combo_cur = combo_next;       // consume previous load

        // issue next quantum's attr load EARLY (independent of stores below)
        if (qn < nqf && lane < QUANT) {
            int2 a = attr[qn * QUANT + lane];
            combo_next = ((a.x & 3) << 2) | (a.y & 3);
        }

        // QUANT independent 512B streaming row-stores for quantum q
        const int base = q * QUANT;
        #pragma unroll
        for (int r = 0; r < QUANT; r++) {
            int combo = __shfl_sync(0xFFFFFFFFu, combo_cur, r);
            float4 v = *(const float4*)&lut_s[combo * H_DIM + lane * 4];
            __stcs((float4*)&out[(size_t)(base + r) * H_DIM + lane * 4], v);
        }

        q = qn;
    }

    // tail rows (n % QUANT) — warp 0 only (0 rows for n = 1e6)
    if (gwarp == 0) {
        for (int row = nqf * QUANT; row < n; row++) {
            int2 a = attr[row];
            int combo = ((a.x & 3) << 2) | (a.y & 3);
            float4 v = *(const float4*)&lut_s[combo * H_DIM + lane * 4];
            __stcs((float4*)&out[(size_t)row * H_DIM + lane * 4], v);
        }
    }
}

// ---------------------------------------------------------------------------
// Launch
// Inputs (metadata order): clique_attr int32 [N,2], emb_table f32 [4,64],
//                          W f32 [4,32,64], b f32 [4,64]
// Output: float32 [N,128]
// ---------------------------------------------------------------------------
extern "C" void kernel_launch(void* const* d_in, const int* in_sizes, int n_in,
                              void* d_out, int out_size)
{
    const int2*  attr      = (const int2*)d_in[0];
    const float* emb_table = (const float*)d_in[1];
    const float* W         = (const float*)d_in[2];
    const float* b         = (const float*)d_in[3];
    float*       out       = (float*)d_out;

    const int n = in_sizes[0] / 2;

    const int blocks = 148 * 8;                 // one full resident wave
    clique_encoder_kernel<<<blocks, 256>>>(attr, emb_table, W, b, out, n);
}

// round 9
// speedup vs baseline: 1.2987x; 1.0151x over previous
#include <cuda_runtime.h>
#include <cuda_bf16.h>

// Problem constants (match reference)
#define H_DIM   128
#define RBF_N   32
#define H2_DIM  64      // H - H//2
#define MAX_D   20.0f
#define NCOMBO  16      // 4 types x 4 distances (randint(0,4) both columns)
#define QUANT   8       // rows per work quantum

// ---------------------------------------------------------------------------
// Single fused kernel.
// Prologue: build the 16x128 LUT in shared from the tiny weight tensors.
// Body:     interleaved grid-stride over 8-row quanta, processed in BATCHES
//           OF 4 with one-batch-ahead prefetch:
//             - attr reads come in MLP-4 bursts every 16KB of stores per warp
//               (4x fewer DRAM read/write turnaround points than R8)
//             - load latency hidden behind 4 quanta (~32 stores) of work
//           Stores: STG.128 .cs per lane (512B contiguous per warp-instr).
// Launch:   740 blocks (5/SM) — regs grow past 32 for the batch registers,
//           so no min-blocks bound; single fully-resident wave.
// ---------------------------------------------------------------------------
__global__ void __launch_bounds__(256)
clique_encoder_kernel(const int2* __restrict__ attr,        // [N] (t, d)
                      const float* __restrict__ emb_table,  // [4][64]
                      const float* __restrict__ W,           // [4][32][64]
                      const float* __restrict__ b,           // [4][64]
                      float* __restrict__ out,               // [N][128]
                      int n)
{
    __shared__ float basis_s[4 * RBF_N];        // 4 distances x 32 rbf
    __shared__ float lut_s[NCOMBO * H_DIM];     // 8 KB

    const int tid = threadIdx.x;

    // --- gaussian basis for the 4 possible integer distances ---
    if (tid < 4 * RBF_N) {
        const int dI = tid >> 5;
        const int k  = tid & 31;
        const float center = MAX_D * (float)k / 31.0f;
        const float diff   = (float)dI - center;
        const float inv2s2 = 0.5f * (31.0f / MAX_D) * (31.0f / MAX_D); // 1/(2*std^2)
        basis_s[tid] = __expf(-diff * diff * inv2s2);
    }
    __syncthreads();

    // --- build 16x128 LUT: 2048 entries, 8 per thread ---
    for (int e = tid; e < NCOMBO * H_DIM; e += 256) {
        const int combo = e >> 7;               // 0..15
        const int j     = e & 127;              // 0..127
        const int t  = combo >> 2;
        const int dI = combo & 3;
        float v;
        if (j < 64) {
            v = emb_table[t * 64 + j];
        } else {
            const int c = j - 64;
            float acc = b[t * H2_DIM + c];
            #pragma unroll
            for (int k = 0; k < RBF_N; k++)
                acc += basis_s[dI * RBF_N + k] * W[(t * RBF_N + k) * H2_DIM + c];
            v = acc;
        }
        lut_s[e] = v;
    }
    __syncthreads();

    // --- batched-prefetch interleaved scatter ---
    const int lane   = tid & 31;
    const int gwarp  = (blockIdx.x * blockDim.x + tid) >> 5;
    const int nwarps = (gridDim.x * blockDim.x) >> 5;
    const int st     = nwarps;

    const int nqf = n / QUANT;                  // full quanta (125000 for 1e6)

    // helpers (inlined)
    #define LDCOMBO(qidx, dst) do {                                   \
        int _c = 0;                                                    \
        if (lane < QUANT) {                                            \
            int2 _a = attr[(qidx) * QUANT + lane];                     \
            _c = ((_a.x & 3) << 2) | (_a.y & 3);                       \
        }                                                              \
        (dst) = _c;                                                    \
    } while (0)

    #define STORE8(qidx, combo_l) do {                                 \
        const int _base = (qidx) * QUANT;                              \
        _Pragma("unroll")                                              \
        for (int _r = 0; _r < QUANT; _r++) {                           \
            int _combo = __shfl_sync(0xFFFFFFFFu, (combo_l), _r);      \
            float4 _v = *(const float4*)&lut_s[_combo * H_DIM + lane * 4]; \
            __stcs((float4*)&out[(size_t)(_base + _r) * H_DIM + lane * 4], _v); \
        }                                                              \
    } while (0)

    int q = gwarp;
    int c0 = 0, c1 = 0, c2 = 0, c3 = 0;
    bool have = (q + 3 * st < nqf);
    if (have) {                                 // prologue: MLP-4 load burst
        LDCOMBO(q,          c0);
        LDCOMBO(q +     st, c1);
        LDCOMBO(q + 2 * st, c2);
        LDCOMBO(q + 3 * st, c3);
    }

    while (have) {
        const int qn = q + 4 * st;
        int n0 = 0, n1 = 0, n2 = 0, n3 = 0;
        const bool hn = (qn + 3 * st < nqf);
        if (hn) {                               // next batch's loads, issued
            LDCOMBO(qn,          n0);           // BEFORE this batch's stores
            LDCOMBO(qn +     st, n1);
            LDCOMBO(qn + 2 * st, n2);
            LDCOMBO(qn + 3 * st, n3);
        }

        STORE8(q,          c0);                 // 32 independent 512B stores
        STORE8(q +     st, c1);
        STORE8(q + 2 * st, c2);
        STORE8(q + 3 * st, c3);

        q = qn;
        c0 = n0; c1 = n1; c2 = n2; c3 = n3;
        have = hn;
    }

    // remainder quanta (<= 4 per warp): 1-deep prefetch, R8 style
    int cnext = 0;
    if (q < nqf) LDCOMBO(q, cnext);
    while (q < nqf) {
        const int qn = q + st;
        const int ccur = cnext;
        if (qn < nqf) LDCOMBO(qn, cnext);
        STORE8(q, ccur);
        q = qn;
    }

    // tail rows (n % QUANT) — warp 0 only (0 rows for n = 1e6)
    if (gwarp == 0) {
        for (int row = nqf * QUANT; row < n; row++) {
            int2 a = attr[row];
            int combo = ((a.x & 3) << 2) | (a.y & 3);
            float4 v = *(const float4*)&lut_s[combo * H_DIM + lane * 4];
            __stcs((float4*)&out[(size_t)row * H_DIM + lane * 4], v);
        }
    }

    #undef LDCOMBO
    #undef STORE8
}

// ---------------------------------------------------------------------------
// Launch
// Inputs (metadata order): clique_attr int32 [N,2], emb_table f32 [4,64],
//                          W f32 [4,32,64], b f32 [4,64]
// Output: float32 [N,128]
// ---------------------------------------------------------------------------
extern "C" void kernel_launch(void* const* d_in, const int* in_sizes, int n_in,
                              void* d_out, int out_size)
{
    const int2*  attr      = (const int2*)d_in[0];
    const float* emb_table = (const float*)d_in[1];
    const float* W         = (const float*)d_in[2];
    const float* b         = (const float*)d_in[3];
    float*       out       = (float*)d_out;

    const int n = in_sizes[0] / 2;

    const int blocks = 148 * 5;                 // one fully-resident wave @ ~48 regs
    clique_encoder_kernel<<<blocks, 256>>>(attr, emb_table, W, b, out, n);
}